// round 14
// baseline (speedup 1.0000x reference)
#include <cuda_runtime.h>
#include <stdint.h>
#include <math.h>

#define B_   8
#define H_   64
#define W_   64
#define DIM_ 768
#define MID_ 96
#define HW_  (H_*W_)            // 4096
#define TOK_ (B_*HW_)           // 32768
#define NTAP 49                 // 7x7

// ---------------- scratch (device globals: no allocation allowed) ----------
__device__ float g_x_emb [TOK_*MID_];
__device__ float g_t_emb [TOK_*MID_];
__device__ float g_y     [TOK_*MID_];
__device__ float g_style [TOK_*2*MID_];
__device__ float g_conv  [TOK_*MID_];
__device__ float g_part  [B_*32*MID_];   // gvec partial sums (deterministic)
__device__ float g_dyn   [B_*MID_*NTAP]; // [b][c][tap]  (tap-contiguous)

// ---------------- tf32 mma + cp.async helpers ------------------------------
__device__ __forceinline__ float to_tf32(float x) {
    uint32_t u;
    asm("cvt.rna.tf32.f32 %0, %1;" : "=r"(u) : "f"(x));
    return __uint_as_float(u);
}

__device__ __forceinline__ void mma_tf32(float* c, const uint32_t* a,
                                         uint32_t b0, uint32_t b1) {
    asm volatile(
        "mma.sync.aligned.m16n8k8.row.col.f32.tf32.tf32.f32 "
        "{%0,%1,%2,%3}, {%4,%5,%6,%7}, {%8,%9}, {%0,%1,%2,%3};"
        : "+f"(c[0]), "+f"(c[1]), "+f"(c[2]), "+f"(c[3])
        : "r"(a[0]), "r"(a[1]), "r"(a[2]), "r"(a[3]), "r"(b0), "r"(b1));
}

__device__ __forceinline__ void cp16(void* dst_smem, const void* src) {
    uint32_t d = (uint32_t)__cvta_generic_to_shared(dst_smem);
    asm volatile("cp.async.cg.shared.global [%0], [%1], 16;" :: "r"(d), "l"(src));
}
#define CP_COMMIT() asm volatile("cp.async.commit_group;")
#define CP_WAIT1()  asm volatile("cp.async.wait_group 1;")
#define CP_WAIT0()  asm volatile("cp.async.wait_group 0;")

// ===========================================================================
// Kernel 1: fused LayerNorm(768) + Linear(768->96), tf32 TC, cp.async 2-stage.
// LN weight/bias read via __ldg at consume time (saves 6KB smem -> 2 CTA/SM).
// ===========================================================================
__global__ __launch_bounds__(256) void ln_down_tc(
    const float* __restrict__ X, const float* __restrict__ lnw,
    const float* __restrict__ lnb, const float* __restrict__ Wd,
    const float* __restrict__ bd, float* __restrict__ out)
{
    const int TM = 128, KT = 16, LDS_ = KT + 4;   // stride 20: conflict-free
    const int NIT = DIM_ / KT;                    // 48
    __shared__ __align__(16) float A_s[2][TM][LDS_];
    __shared__ __align__(16) float B_s[2][MID_][LDS_];
    __shared__ float mean_s[TM], rstd_s[TM];

    int tid  = threadIdx.x;
    int tok0 = blockIdx.x * TM;

    // ---- prologue: async-load tile 0 (overlaps the stats pass below) ----
    {
        #pragma unroll
        for (int r = 0; r < 2; r++) {
            int idx = tid + r * 256;
            int m = idx >> 2, k4 = (idx & 3) * 4;
            cp16(&A_s[0][m][k4], X + (size_t)(tok0 + m) * DIM_ + k4);
        }
        for (int idx = tid; idx < 384; idx += 256) {
            int n = idx >> 2, k4 = (idx & 3) * 4;
            cp16(&B_s[0][n][k4], Wd + (size_t)n * DIM_ + k4);
        }
        CP_COMMIT();
    }

    // ---- per-token LN stats (warp per token) ----
    int w = tid >> 5, lane = tid & 31;
    for (int m = w; m < TM; m += 8) {
        const float* row = X + (size_t)(tok0 + m) * DIM_;
        float s = 0.f, s2 = 0.f;
        #pragma unroll 4
        for (int k = lane; k < DIM_; k += 32) { float v = row[k]; s += v; s2 += v*v; }
        #pragma unroll
        for (int off = 16; off; off >>= 1) {
            s  += __shfl_down_sync(0xffffffffu, s,  off);
            s2 += __shfl_down_sync(0xffffffffu, s2, off);
        }
        if (lane == 0) {
            float mu  = s  * (1.f / DIM_);
            float var = s2 * (1.f / DIM_) - mu * mu;
            mean_s[m] = mu;
            rstd_s[m] = rsqrtf(var + 1e-6f);
        }
    }
    __syncthreads();

    int wm = w & 3, wn = w >> 2;
    int mb = wm * 32, nb = wn * 48;
    int gr = lane >> 2, gc = lane & 3;

    float acc[2][6][4];
    #pragma unroll
    for (int i = 0; i < 2; i++)
        #pragma unroll
        for (int j = 0; j < 6; j++)
            #pragma unroll
            for (int r = 0; r < 4; r++) acc[i][j][r] = 0.f;

    for (int it = 0; it < NIT; it++) {
        int s = it & 1;
        if (it + 1 < NIT) {
            int kt = (it + 1) * KT;
            #pragma unroll
            for (int r = 0; r < 2; r++) {
                int idx = tid + r * 256;
                int m = idx >> 2, k4 = (idx & 3) * 4;
                cp16(&A_s[s ^ 1][m][k4], X + (size_t)(tok0 + m) * DIM_ + kt + k4);
            }
            for (int idx = tid; idx < 384; idx += 256) {
                int n = idx >> 2, k4 = (idx & 3) * 4;
                cp16(&B_s[s ^ 1][n][k4], Wd + (size_t)n * DIM_ + kt + k4);
            }
            CP_COMMIT();
            CP_WAIT1();
        } else {
            CP_WAIT0();
        }
        __syncthreads();

        int kt = it * KT;
        #pragma unroll
        for (int ks = 0; ks < 2; ks++) {
            int k0 = ks * 8;
            float w0 = __ldg(lnw + kt + k0 + gc),     bb0 = __ldg(lnb + kt + k0 + gc);
            float w4 = __ldg(lnw + kt + k0 + gc + 4), bb4 = __ldg(lnb + kt + k0 + gc + 4);
            uint32_t a[2][4];
            #pragma unroll
            for (int mi = 0; mi < 2; mi++) {
                int r0 = mb + mi * 16 + gr;
                float mu0 = mean_s[r0],     rs0 = rstd_s[r0];
                float mu8 = mean_s[r0 + 8], rs8 = rstd_s[r0 + 8];
                a[mi][0] = __float_as_uint(to_tf32((A_s[s][r0    ][k0 + gc    ] - mu0) * rs0 * w0 + bb0));
                a[mi][1] = __float_as_uint(to_tf32((A_s[s][r0 + 8][k0 + gc    ] - mu8) * rs8 * w0 + bb0));
                a[mi][2] = __float_as_uint(to_tf32((A_s[s][r0    ][k0 + gc + 4] - mu0) * rs0 * w4 + bb4));
                a[mi][3] = __float_as_uint(to_tf32((A_s[s][r0 + 8][k0 + gc + 4] - mu8) * rs8 * w4 + bb4));
            }
            #pragma unroll
            for (int ni = 0; ni < 6; ni++) {
                int n0 = nb + ni * 8 + gr;
                uint32_t b0 = __float_as_uint(to_tf32(B_s[s][n0][k0 + gc    ]));
                uint32_t b1 = __float_as_uint(to_tf32(B_s[s][n0][k0 + gc + 4]));
                mma_tf32(acc[0][ni], a[0], b0, b1);
                mma_tf32(acc[1][ni], a[1], b0, b1);
            }
        }
        __syncthreads();
    }

    #pragma unroll
    for (int mi = 0; mi < 2; mi++) {
        int row = tok0 + mb + mi * 16 + gr;
        #pragma unroll
        for (int ni = 0; ni < 6; ni++) {
            int col = nb + ni * 8 + gc * 2;
            float bz0 = bd[col], bz1 = bd[col + 1];
            out[(size_t)row       * MID_ + col    ] = acc[mi][ni][0] + bz0;
            out[(size_t)row       * MID_ + col + 1] = acc[mi][ni][1] + bz1;
            out[(size_t)(row + 8) * MID_ + col    ] = acc[mi][ni][2] + bz0;
            out[(size_t)(row + 8) * MID_ + col + 1] = acc[mi][ni][3] + bz1;
        }
    }
}

// ===========================================================================
// Kernel 2: gvec partial sums over 128-token chunks (deterministic)
// ===========================================================================
__global__ void gsum_kernel()
{
    int b = blockIdx.x >> 5;
    int chunk = blockIdx.x & 31;
    int c = threadIdx.x;
    int tok0 = b * HW_ + chunk * 128;
    float s = 0.f;
    #pragma unroll 4
    for (int m = 0; m < 128; m++) s += g_x_emb[(size_t)(tok0 + m) * MID_ + c];
    g_part[(b * 32 + chunk) * MID_ + c] = s;
}

// ===========================================================================
// Kernel 3: per-batch MLP -> softmax -> dyn[b][c][tap].  256 threads.
// ===========================================================================
__global__ __launch_bounds__(256) void mlp_dyn_kernel(
    const float* __restrict__ m1w, const float* __restrict__ m1b,
    const float* __restrict__ m2w, const float* __restrict__ m2b,
    const float* __restrict__ basis)
{
    __shared__ float psum[2 * MID_];
    __shared__ float gvec[MID_];
    __shared__ float hid[24];
    __shared__ float wts[4];
    int b = blockIdx.x, tid = threadIdx.x;
    int w = tid >> 5, lane = tid & 31;

    if (tid < 2 * MID_) {
        int c = tid % MID_, half = tid / MID_;
        float s = 0.f;
        #pragma unroll
        for (int ch = 0; ch < 16; ch++)
            s += g_part[(b * 32 + half * 16 + ch) * MID_ + c];
        psum[tid] = s;
    }
    __syncthreads();
    if (tid < MID_) gvec[tid] = (psum[tid] + psum[MID_ + tid]) * (1.f / HW_);
    __syncthreads();

    // 8 warps x 3 hidden units each
    #pragma unroll
    for (int sub = 0; sub < 3; sub++) {
        int h = w * 3 + sub;   // 0..23
        const float* wr = m1w + h * MID_;
        float s = gvec[lane] * wr[lane]
                + gvec[lane + 32] * wr[lane + 32]
                + gvec[lane + 64] * wr[lane + 64];
        #pragma unroll
        for (int off = 16; off; off >>= 1)
            s += __shfl_down_sync(0xffffffffu, s, off);
        if (lane == 0) hid[h] = fmaxf(s + m1b[h], 0.f);
    }
    __syncthreads();

    if (tid < 4) {
        float s = m2b[tid];
        #pragma unroll
        for (int h = 0; h < 24; h++) s += hid[h] * m2w[tid * 24 + h];
        wts[tid] = s;
    }
    __syncthreads();
    if (tid == 0) {
        float mx = fmaxf(fmaxf(wts[0], wts[1]), fmaxf(wts[2], wts[3]));
        float e0 = expf(wts[0]-mx), e1 = expf(wts[1]-mx);
        float e2 = expf(wts[2]-mx), e3 = expf(wts[3]-mx);
        float inv = 1.f / (e0 + e1 + e2 + e3);
        wts[0] = e0*inv; wts[1] = e1*inv; wts[2] = e2*inv; wts[3] = e3*inv;
    }
    __syncthreads();
    float w0 = wts[0], w1 = wts[1], w2 = wts[2], w3 = wts[3];
    for (int idx = tid; idx < MID_ * NTAP; idx += 256) {
        float s = w0 * basis[(size_t)(0 * MID_ * NTAP) + idx]
                + w1 * basis[(size_t)(1 * MID_ * NTAP) + idx]
                + w2 * basis[(size_t)(2 * MID_ * NTAP) + idx]
                + w3 * basis[(size_t)(3 * MID_ * NTAP) + idx];
        g_dyn[(size_t)b * MID_ * NTAP + idx] = s;
    }
}

// ===========================================================================
// Kernel 4: depthwise 3x3 conv (zero pad) + bias + SiLU, NHWC
// ===========================================================================
__global__ __launch_bounds__(256) void dw_silu_kernel(
    const float* __restrict__ dww, const float* __restrict__ dwb)
{
    __shared__ float w_s[MID_ * 9];
    __shared__ float b_s[MID_];
    int tid = threadIdx.x;
    for (int i = tid; i < MID_ * 9; i += 256) w_s[i] = dww[i];
    if (tid < MID_) b_s[tid] = dwb[tid];
    __syncthreads();

    int e = blockIdx.x * 256 + tid;          // < TOK_*MID_
    int c = e % MID_;
    int token = e / MID_;
    int b = token >> 12, i = (token >> 6) & 63, j = token & 63;
    float acc = b_s[c];
    #pragma unroll
    for (int di = -1; di <= 1; di++) {
        int ii = i + di;
        if (ii < 0 || ii > 63) continue;
        #pragma unroll
        for (int dj = -1; dj <= 1; dj++) {
            int jj = j + dj;
            if (jj < 0 || jj > 63) continue;
            acc += g_t_emb[(size_t)((b << 12) | (ii << 6) | jj) * MID_ + c]
                 * w_s[c * 9 + (di + 1) * 3 + (dj + 1)];
        }
    }
    g_y[e] = acc / (1.f + __expf(-acc));   // silu
}

// ===========================================================================
// Kernel 5: K=96 GEMM, tf32 TC, cp.async 2-stage.  Block 128xTN, KT=16.
// ===========================================================================
template<int TN>
__global__ __launch_bounds__(256) void gemm_k96_tc(
    const float* __restrict__ A, const float* __restrict__ Bw,
    const float* __restrict__ bias, const float* __restrict__ resid,
    float* __restrict__ out, int Ntot)
{
    const int TM = 128, KT = 16, LDS_ = KT + 4;
    const int NIT = MID_ / KT;   // 6
    const int NI  = TN / 16;     // MMAs per warp per ks
    __shared__ __align__(16) float A_s[2][TM][LDS_];
    __shared__ __align__(16) float B_s[2][TN][LDS_];

    int tid  = threadIdx.x;
    int tok0 = blockIdx.x * TM;
    int nblk = blockIdx.y * TN;

    // prologue: tile 0
    {
        #pragma unroll
        for (int r = 0; r < 2; r++) {
            int idx = tid + r * 256;
            int m = idx >> 2, k4 = (idx & 3) * 4;
            cp16(&A_s[0][m][k4], A + (size_t)(tok0 + m) * MID_ + k4);
        }
        #pragma unroll
        for (int r = 0; r < TN / 64; r++) {
            int idx = tid + r * 256;
            int n = idx >> 2, k4 = (idx & 3) * 4;
            cp16(&B_s[0][n][k4], Bw + (size_t)(nblk + n) * MID_ + k4);
        }
        CP_COMMIT();
    }

    int w = tid >> 5, lane = tid & 31;
    int wm = w & 3, wn = w >> 2;
    int mb = wm * 32, nb = wn * (TN / 2);
    int gr = lane >> 2, gc = lane & 3;

    float acc[2][NI][4];
    #pragma unroll
    for (int i = 0; i < 2; i++)
        #pragma unroll
        for (int j = 0; j < NI; j++)
            #pragma unroll
            for (int r = 0; r < 4; r++) acc[i][j][r] = 0.f;

    #pragma unroll
    for (int it = 0; it < NIT; it++) {
        int s = it & 1;
        if (it + 1 < NIT) {
            int kt = (it + 1) * KT;
            #pragma unroll
            for (int r = 0; r < 2; r++) {
                int idx = tid + r * 256;
                int m = idx >> 2, k4 = (idx & 3) * 4;
                cp16(&A_s[s ^ 1][m][k4], A + (size_t)(tok0 + m) * MID_ + kt + k4);
            }
            #pragma unroll
            for (int r = 0; r < TN / 64; r++) {
                int idx = tid + r * 256;
                int n = idx >> 2, k4 = (idx & 3) * 4;
                cp16(&B_s[s ^ 1][n][k4], Bw + (size_t)(nblk + n) * MID_ + kt + k4);
            }
            CP_COMMIT();
            CP_WAIT1();
        } else {
            CP_WAIT0();
        }
        __syncthreads();

        #pragma unroll
        for (int ks = 0; ks < 2; ks++) {
            int k0 = ks * 8;
            uint32_t a[2][4];
            #pragma unroll
            for (int mi = 0; mi < 2; mi++) {
                int r0 = mb + mi * 16 + gr;
                a[mi][0] = __float_as_uint(to_tf32(A_s[s][r0    ][k0 + gc    ]));
                a[mi][1] = __float_as_uint(to_tf32(A_s[s][r0 + 8][k0 + gc    ]));
                a[mi][2] = __float_as_uint(to_tf32(A_s[s][r0    ][k0 + gc + 4]));
                a[mi][3] = __float_as_uint(to_tf32(A_s[s][r0 + 8][k0 + gc + 4]));
            }
            #pragma unroll
            for (int ni = 0; ni < NI; ni++) {
                int n0 = nb + ni * 8 + gr;
                uint32_t b0 = __float_as_uint(to_tf32(B_s[s][n0][k0 + gc    ]));
                uint32_t b1 = __float_as_uint(to_tf32(B_s[s][n0][k0 + gc + 4]));
                mma_tf32(acc[0][ni], a[0], b0, b1);
                mma_tf32(acc[1][ni], a[1], b0, b1);
            }
        }
        __syncthreads();
    }

    #pragma unroll
    for (int mi = 0; mi < 2; mi++) {
        int row = tok0 + mb + mi * 16 + gr;
        #pragma unroll
        for (int ni = 0; ni < NI; ni++) {
            int col = nblk + nb + ni * 8 + gc * 2;
            float bz0 = bias[col], bz1 = bias[col + 1];
            size_t i0 = (size_t)row * Ntot + col;
            size_t i1 = (size_t)(row + 8) * Ntot + col;
            float v00 = acc[mi][ni][0] + bz0, v01 = acc[mi][ni][1] + bz1;
            float v10 = acc[mi][ni][2] + bz0, v11 = acc[mi][ni][3] + bz1;
            if (resid) {
                v00 += resid[i0]; v01 += resid[i0 + 1];
                v10 += resid[i1]; v11 += resid[i1 + 1];
            }
            out[i0] = v00; out[i0 + 1] = v01;
            out[i1] = v10; out[i1 + 1] = v11;
        }
    }
}

// ===========================================================================
// Kernel 6: fused FiLM + 7x7 circular convolution, smem-tiled.
// ===========================================================================
__global__ __launch_bounds__(256) void film_circconv_kernel()
{
    const int TS = 16, HALO = 22, CPG = 16, PSTR = 20; // pixel stride (floats)
    __shared__ __align__(16) float halo_s[HALO * HALO * PSTR]; // 38720 B
    __shared__ __align__(16) float d_s[NTAP * CPG];            //  3136 B

    int tid = threadIdx.x;
    int tile = blockIdx.x;           // 0..15
    int cg   = blockIdx.y;           // 0..5
    int b    = blockIdx.z;           // 0..7
    int i0 = (tile >> 2) * TS, j0 = (tile & 3) * TS;
    int ch0 = cg * CPG;

    // ---- load dyn filter (transpose [c][tap] -> smem [tap][c]) ----
    const float* dynb = g_dyn + ((size_t)b * MID_ + ch0) * NTAP;
    for (int e = tid; e < CPG * NTAP; e += 256) {
        int c = e / NTAP, tap = e % NTAP;
        d_s[tap * CPG + c] = dynb[e];
    }

    // ---- load halo with FiLM applied: common = x*(1+gamma)+beta ----
    for (int e = tid; e < HALO * HALO * 4; e += 256) {
        int pix = e >> 2, c4 = e & 3;
        int li = pix / HALO, lj = pix % HALO;
        int ii = (i0 - 3 + li) & 63;
        int jj = (j0 - 3 + lj) & 63;
        size_t token = (size_t)((b << 12) | (ii << 6) | jj);
        int ch = ch0 + c4 * 4;
        float4 xv = *reinterpret_cast<const float4*>(g_x_emb + token * MID_ + ch);
        float4 gm = *reinterpret_cast<const float4*>(g_style + token * (2*MID_) + ch);
        float4 bt = *reinterpret_cast<const float4*>(g_style + token * (2*MID_) + MID_ + ch);
        float4 cv;
        cv.x = xv.x * (1.f + gm.x) + bt.x;
        cv.y = xv.y * (1.f + gm.y) + bt.y;
        cv.z = xv.z * (1.f + gm.z) + bt.z;
        cv.w = xv.w * (1.f + gm.w) + bt.w;
        *reinterpret_cast<float4*>(halo_s + pix * PSTR + c4 * 4) = cv;
    }
    __syncthreads();

    // ---- compute: thread = one output pixel ----
    int pi = tid >> 4, pj = tid & 15;
    size_t tok_out = (size_t)((b << 12) | ((i0 + pi) << 6) | (j0 + pj));
    float* outp = g_conv + tok_out * MID_ + ch0;

    #pragma unroll
    for (int c4 = 0; c4 < 4; c4++) {
        float4 acc = make_float4(0.f, 0.f, 0.f, 0.f);
        #pragma unroll
        for (int di = 0; di < 7; di++) {
            int hi = pi + 6 - di;
            #pragma unroll
            for (int dj = 0; dj < 7; dj++) {
                int hj = pj + 6 - dj;
                float4 v = *reinterpret_cast<const float4*>(
                    halo_s + (hi * HALO + hj) * PSTR + c4 * 4);
                float4 d = *reinterpret_cast<const float4*>(
                    d_s + (di * 7 + dj) * CPG + c4 * 4);
                acc.x += d.x * v.x; acc.y += d.y * v.y;
                acc.z += d.z * v.z; acc.w += d.w * v.w;
            }
        }
        *reinterpret_cast<float4*>(outp + c4 * 4) = acc;
    }
}

// ===========================================================================
extern "C" void kernel_launch(void* const* d_in, const int* in_sizes, int n_in,
                              void* d_out, int out_size)
{
    const float* x      = (const float*)d_in[0];
    const float* t      = (const float*)d_in[1];
    const float* ln_w   = (const float*)d_in[2];
    const float* ln_b   = (const float*)d_in[3];
    const float* down_w = (const float*)d_in[4];
    const float* down_b = (const float*)d_in[5];
    const float* ln1_w  = (const float*)d_in[6];
    const float* ln1_b  = (const float*)d_in[7];
    const float* down1_w= (const float*)d_in[8];
    const float* down1_b= (const float*)d_in[9];
    const float* dw_w   = (const float*)d_in[10];
    const float* dw_b   = (const float*)d_in[11];
    const float* pw_w   = (const float*)d_in[12];
    const float* pw_b   = (const float*)d_in[13];
    const float* m1w    = (const float*)d_in[14];
    const float* m1b    = (const float*)d_in[15];
    const float* m2w    = (const float*)d_in[16];
    const float* m2b    = (const float*)d_in[17];
    const float* basis  = (const float*)d_in[18];
    const float* up_w   = (const float*)d_in[19];
    const float* up_b   = (const float*)d_in[20];
    float* out = (float*)d_out;

    float *p_x_emb, *p_t_emb, *p_y, *p_style, *p_conv;
    cudaGetSymbolAddress((void**)&p_x_emb,  g_x_emb);
    cudaGetSymbolAddress((void**)&p_t_emb,  g_t_emb);
    cudaGetSymbolAddress((void**)&p_y,      g_y);
    cudaGetSymbolAddress((void**)&p_style,  g_style);
    cudaGetSymbolAddress((void**)&p_conv,   g_conv);

    // down / down1 (fused LN + GEMM, tf32 tensor cores, cp.async pipelined)
    ln_down_tc<<<TOK_/128, 256>>>(x, ln_w,  ln_b,  down_w,  down_b,  p_x_emb);
    ln_down_tc<<<TOK_/128, 256>>>(t, ln1_w, ln1_b, down1_w, down1_b, p_t_emb);

    // head path first (reordered so ncu -s5 lands on a GEMM launch)
    dw_silu_kernel<<<(TOK_*MID_)/256, 256>>>(dw_w, dw_b);
    gemm_k96_tc<64><<<dim3(TOK_/128, (2*MID_)/64), 256>>>(
        p_y, pw_w, pw_b, nullptr, p_style, 2*MID_);

    // FDS weights path (independent of head path)
    gsum_kernel<<<B_*32, 96>>>();
    mlp_dyn_kernel<<<B_, 256>>>(m1w, m1b, m2w, m2b, basis);

    // fused FiLM + 7x7 circular conv (smem-tiled)
    film_circconv_kernel<<<dim3(16, 6, 8), 256>>>();

    // up projection + residual (TN=128)
    gemm_k96_tc<128><<<dim3(TOK_/128, DIM_/128), 256>>>(
        p_conv, up_w, up_b, x, out, DIM_);
}

// round 15
// speedup vs baseline: 1.0489x; 1.0489x over previous
#include <cuda_runtime.h>
#include <stdint.h>
#include <math.h>

#define B_   8
#define H_   64
#define W_   64
#define DIM_ 768
#define MID_ 96
#define HW_  (H_*W_)            // 4096
#define TOK_ (B_*HW_)           // 32768
#define NTAP 49                 // 7x7

// ---------------- scratch (device globals: no allocation allowed) ----------
__device__ float g_x_emb [TOK_*MID_];
__device__ float g_t_emb [TOK_*MID_];
__device__ float g_y     [TOK_*MID_];
__device__ float g_style [TOK_*2*MID_];
__device__ float g_conv  [TOK_*MID_];
__device__ float g_part  [B_*32*MID_];   // gvec partial sums (deterministic)
__device__ float g_dyn   [B_*MID_*NTAP]; // [b][c][tap]  (tap-contiguous)

// ---------------- tf32 mma + cp.async helpers ------------------------------
__device__ __forceinline__ float to_tf32(float x) {
    uint32_t u;
    asm("cvt.rna.tf32.f32 %0, %1;" : "=r"(u) : "f"(x));
    return __uint_as_float(u);
}

__device__ __forceinline__ void mma_tf32(float* c, const uint32_t* a,
                                         uint32_t b0, uint32_t b1) {
    asm volatile(
        "mma.sync.aligned.m16n8k8.row.col.f32.tf32.tf32.f32 "
        "{%0,%1,%2,%3}, {%4,%5,%6,%7}, {%8,%9}, {%0,%1,%2,%3};"
        : "+f"(c[0]), "+f"(c[1]), "+f"(c[2]), "+f"(c[3])
        : "r"(a[0]), "r"(a[1]), "r"(a[2]), "r"(a[3]), "r"(b0), "r"(b1));
}

__device__ __forceinline__ void cp16(void* dst_smem, const void* src) {
    uint32_t d = (uint32_t)__cvta_generic_to_shared(dst_smem);
    asm volatile("cp.async.cg.shared.global [%0], [%1], 16;" :: "r"(d), "l"(src));
}
#define CP_COMMIT() asm volatile("cp.async.commit_group;")
#define CP_WAIT1()  asm volatile("cp.async.wait_group 1;")
#define CP_WAIT0()  asm volatile("cp.async.wait_group 0;")

// ===========================================================================
// Kernel 1: fused LayerNorm(768) + Linear(768->96), tf32 TC, cp.async 2-stage.
// (R10-proven config: LN params staged in smem, RNA tf32 rounding.)
// ===========================================================================
__global__ __launch_bounds__(256) void ln_down_tc(
    const float* __restrict__ X, const float* __restrict__ lnw,
    const float* __restrict__ lnb, const float* __restrict__ Wd,
    const float* __restrict__ bd, float* __restrict__ out)
{
    const int TM = 128, KT = 16, LDS_ = KT + 4;   // stride 20: conflict-free
    const int NIT = DIM_ / KT;                    // 48
    __shared__ __align__(16) float A_s[2][TM][LDS_];
    __shared__ __align__(16) float B_s[2][MID_][LDS_];
    __shared__ float mean_s[TM], rstd_s[TM];
    __shared__ float lnw_s[DIM_], lnb_s[DIM_];

    int tid  = threadIdx.x;
    int tok0 = blockIdx.x * TM;

    // ---- prologue: async-load tile 0 (overlaps the stats pass below) ----
    {
        #pragma unroll
        for (int r = 0; r < 2; r++) {
            int idx = tid + r * 256;
            int m = idx >> 2, k4 = (idx & 3) * 4;
            cp16(&A_s[0][m][k4], X + (size_t)(tok0 + m) * DIM_ + k4);
        }
        for (int idx = tid; idx < 384; idx += 256) {
            int n = idx >> 2, k4 = (idx & 3) * 4;
            cp16(&B_s[0][n][k4], Wd + (size_t)n * DIM_ + k4);
        }
        CP_COMMIT();
    }

    for (int i = tid; i < DIM_; i += 256) { lnw_s[i] = lnw[i]; lnb_s[i] = lnb[i]; }

    // ---- per-token LN stats (warp per token) ----
    int w = tid >> 5, lane = tid & 31;
    for (int m = w; m < TM; m += 8) {
        const float* row = X + (size_t)(tok0 + m) * DIM_;
        float s = 0.f, s2 = 0.f;
        #pragma unroll 4
        for (int k = lane; k < DIM_; k += 32) { float v = row[k]; s += v; s2 += v*v; }
        #pragma unroll
        for (int off = 16; off; off >>= 1) {
            s  += __shfl_down_sync(0xffffffffu, s,  off);
            s2 += __shfl_down_sync(0xffffffffu, s2, off);
        }
        if (lane == 0) {
            float mu  = s  * (1.f / DIM_);
            float var = s2 * (1.f / DIM_) - mu * mu;
            mean_s[m] = mu;
            rstd_s[m] = rsqrtf(var + 1e-6f);
        }
    }
    __syncthreads();

    int wm = w & 3, wn = w >> 2;
    int mb = wm * 32, nb = wn * 48;
    int gr = lane >> 2, gc = lane & 3;

    float acc[2][6][4];
    #pragma unroll
    for (int i = 0; i < 2; i++)
        #pragma unroll
        for (int j = 0; j < 6; j++)
            #pragma unroll
            for (int r = 0; r < 4; r++) acc[i][j][r] = 0.f;

    for (int it = 0; it < NIT; it++) {
        int s = it & 1;
        if (it + 1 < NIT) {
            int kt = (it + 1) * KT;
            #pragma unroll
            for (int r = 0; r < 2; r++) {
                int idx = tid + r * 256;
                int m = idx >> 2, k4 = (idx & 3) * 4;
                cp16(&A_s[s ^ 1][m][k4], X + (size_t)(tok0 + m) * DIM_ + kt + k4);
            }
            for (int idx = tid; idx < 384; idx += 256) {
                int n = idx >> 2, k4 = (idx & 3) * 4;
                cp16(&B_s[s ^ 1][n][k4], Wd + (size_t)n * DIM_ + kt + k4);
            }
            CP_COMMIT();
            CP_WAIT1();
        } else {
            CP_WAIT0();
        }
        __syncthreads();

        int kt = it * KT;
        #pragma unroll
        for (int ks = 0; ks < 2; ks++) {
            int k0 = ks * 8;
            float w0 = lnw_s[kt + k0 + gc],     bb0 = lnb_s[kt + k0 + gc];
            float w4 = lnw_s[kt + k0 + gc + 4], bb4 = lnb_s[kt + k0 + gc + 4];
            uint32_t a[2][4];
            #pragma unroll
            for (int mi = 0; mi < 2; mi++) {
                int r0 = mb + mi * 16 + gr;
                float mu0 = mean_s[r0],     rs0 = rstd_s[r0];
                float mu8 = mean_s[r0 + 8], rs8 = rstd_s[r0 + 8];
                a[mi][0] = __float_as_uint(to_tf32((A_s[s][r0    ][k0 + gc    ] - mu0) * rs0 * w0 + bb0));
                a[mi][1] = __float_as_uint(to_tf32((A_s[s][r0 + 8][k0 + gc    ] - mu8) * rs8 * w0 + bb0));
                a[mi][2] = __float_as_uint(to_tf32((A_s[s][r0    ][k0 + gc + 4] - mu0) * rs0 * w4 + bb4));
                a[mi][3] = __float_as_uint(to_tf32((A_s[s][r0 + 8][k0 + gc + 4] - mu8) * rs8 * w4 + bb4));
            }
            #pragma unroll
            for (int ni = 0; ni < 6; ni++) {
                int n0 = nb + ni * 8 + gr;
                uint32_t b0 = __float_as_uint(to_tf32(B_s[s][n0][k0 + gc    ]));
                uint32_t b1 = __float_as_uint(to_tf32(B_s[s][n0][k0 + gc + 4]));
                mma_tf32(acc[0][ni], a[0], b0, b1);
                mma_tf32(acc[1][ni], a[1], b0, b1);
            }
        }
        __syncthreads();
    }

    #pragma unroll
    for (int mi = 0; mi < 2; mi++) {
        int row = tok0 + mb + mi * 16 + gr;
        #pragma unroll
        for (int ni = 0; ni < 6; ni++) {
            int col = nb + ni * 8 + gc * 2;
            float bz0 = bd[col], bz1 = bd[col + 1];
            out[(size_t)row       * MID_ + col    ] = acc[mi][ni][0] + bz0;
            out[(size_t)row       * MID_ + col + 1] = acc[mi][ni][1] + bz1;
            out[(size_t)(row + 8) * MID_ + col    ] = acc[mi][ni][2] + bz0;
            out[(size_t)(row + 8) * MID_ + col + 1] = acc[mi][ni][3] + bz1;
        }
    }
}

// ===========================================================================
// Kernel 2: gvec partial sums over 128-token chunks (deterministic)
// ===========================================================================
__global__ void gsum_kernel()
{
    int b = blockIdx.x >> 5;
    int chunk = blockIdx.x & 31;
    int c = threadIdx.x;
    int tok0 = b * HW_ + chunk * 128;
    float s = 0.f;
    #pragma unroll 4
    for (int m = 0; m < 128; m++) s += g_x_emb[(size_t)(tok0 + m) * MID_ + c];
    g_part[(b * 32 + chunk) * MID_ + c] = s;
}

// ===========================================================================
// Kernel 3: per-batch MLP -> softmax -> dyn[b][c][tap].  256 threads.
// ===========================================================================
__global__ __launch_bounds__(256) void mlp_dyn_kernel(
    const float* __restrict__ m1w, const float* __restrict__ m1b,
    const float* __restrict__ m2w, const float* __restrict__ m2b,
    const float* __restrict__ basis)
{
    __shared__ float psum[2 * MID_];
    __shared__ float gvec[MID_];
    __shared__ float hid[24];
    __shared__ float wts[4];
    int b = blockIdx.x, tid = threadIdx.x;
    int w = tid >> 5, lane = tid & 31;

    if (tid < 2 * MID_) {
        int c = tid % MID_, half = tid / MID_;
        float s = 0.f;
        #pragma unroll
        for (int ch = 0; ch < 16; ch++)
            s += g_part[(b * 32 + half * 16 + ch) * MID_ + c];
        psum[tid] = s;
    }
    __syncthreads();
    if (tid < MID_) gvec[tid] = (psum[tid] + psum[MID_ + tid]) * (1.f / HW_);
    __syncthreads();

    #pragma unroll
    for (int sub = 0; sub < 3; sub++) {
        int h = w * 3 + sub;   // 0..23
        const float* wr = m1w + h * MID_;
        float s = gvec[lane] * wr[lane]
                + gvec[lane + 32] * wr[lane + 32]
                + gvec[lane + 64] * wr[lane + 64];
        #pragma unroll
        for (int off = 16; off; off >>= 1)
            s += __shfl_down_sync(0xffffffffu, s, off);
        if (lane == 0) hid[h] = fmaxf(s + m1b[h], 0.f);
    }
    __syncthreads();

    if (tid < 4) {
        float s = m2b[tid];
        #pragma unroll
        for (int h = 0; h < 24; h++) s += hid[h] * m2w[tid * 24 + h];
        wts[tid] = s;
    }
    __syncthreads();
    if (tid == 0) {
        float mx = fmaxf(fmaxf(wts[0], wts[1]), fmaxf(wts[2], wts[3]));
        float e0 = expf(wts[0]-mx), e1 = expf(wts[1]-mx);
        float e2 = expf(wts[2]-mx), e3 = expf(wts[3]-mx);
        float inv = 1.f / (e0 + e1 + e2 + e3);
        wts[0] = e0*inv; wts[1] = e1*inv; wts[2] = e2*inv; wts[3] = e3*inv;
    }
    __syncthreads();
    float w0 = wts[0], w1 = wts[1], w2 = wts[2], w3 = wts[3];
    for (int idx = tid; idx < MID_ * NTAP; idx += 256) {
        float s = w0 * basis[(size_t)(0 * MID_ * NTAP) + idx]
                + w1 * basis[(size_t)(1 * MID_ * NTAP) + idx]
                + w2 * basis[(size_t)(2 * MID_ * NTAP) + idx]
                + w3 * basis[(size_t)(3 * MID_ * NTAP) + idx];
        g_dyn[(size_t)b * MID_ * NTAP + idx] = s;
    }
}

// ===========================================================================
// Kernel 4: depthwise 3x3 conv (zero pad) + bias + SiLU, NHWC
// ===========================================================================
__global__ __launch_bounds__(256) void dw_silu_kernel(
    const float* __restrict__ dww, const float* __restrict__ dwb)
{
    __shared__ float w_s[MID_ * 9];
    __shared__ float b_s[MID_];
    int tid = threadIdx.x;
    for (int i = tid; i < MID_ * 9; i += 256) w_s[i] = dww[i];
    if (tid < MID_) b_s[tid] = dwb[tid];
    __syncthreads();

    int e = blockIdx.x * 256 + tid;          // < TOK_*MID_
    int c = e % MID_;
    int token = e / MID_;
    int b = token >> 12, i = (token >> 6) & 63, j = token & 63;
    float acc = b_s[c];
    #pragma unroll
    for (int di = -1; di <= 1; di++) {
        int ii = i + di;
        if (ii < 0 || ii > 63) continue;
        #pragma unroll
        for (int dj = -1; dj <= 1; dj++) {
            int jj = j + dj;
            if (jj < 0 || jj > 63) continue;
            acc += g_t_emb[(size_t)((b << 12) | (ii << 6) | jj) * MID_ + c]
                 * w_s[c * 9 + (di + 1) * 3 + (dj + 1)];
        }
    }
    g_y[e] = acc / (1.f + __expf(-acc));   // silu
}

// ===========================================================================
// Kernel 5: K=96 GEMM, tf32 TC, cp.async 2-stage.  Block 128x64, KT=16.
// __launch_bounds__(256, 4): cap regs at 64 -> 4 CTA/SM (was 3 at 76 regs).
// ===========================================================================
__global__ __launch_bounds__(256, 4) void gemm_k96_tc(
    const float* __restrict__ A, const float* __restrict__ Bw,
    const float* __restrict__ bias, const float* __restrict__ resid,
    float* __restrict__ out, int Ntot)
{
    const int TM = 128, TN = 64, KT = 16, LDS_ = KT + 4;
    const int NIT = MID_ / KT;   // 6
    __shared__ __align__(16) float A_s[2][TM][LDS_];
    __shared__ __align__(16) float B_s[2][TN][LDS_];

    int tid  = threadIdx.x;
    int tok0 = blockIdx.x * TM;
    int nblk = blockIdx.y * TN;

    // prologue: tile 0
    {
        #pragma unroll
        for (int r = 0; r < 2; r++) {
            int idx = tid + r * 256;
            int m = idx >> 2, k4 = (idx & 3) * 4;
            cp16(&A_s[0][m][k4], A + (size_t)(tok0 + m) * MID_ + k4);
        }
        {
            int n = tid >> 2, k4 = (tid & 3) * 4;
            cp16(&B_s[0][n][k4], Bw + (size_t)(nblk + n) * MID_ + k4);
        }
        CP_COMMIT();
    }

    int w = tid >> 5, lane = tid & 31;
    int wm = w & 3, wn = w >> 2;
    int mb = wm * 32, nb = wn * 32;
    int gr = lane >> 2, gc = lane & 3;

    float acc[2][4][4];
    #pragma unroll
    for (int i = 0; i < 2; i++)
        #pragma unroll
        for (int j = 0; j < 4; j++)
            #pragma unroll
            for (int r = 0; r < 4; r++) acc[i][j][r] = 0.f;

    #pragma unroll
    for (int it = 0; it < NIT; it++) {
        int s = it & 1;
        if (it + 1 < NIT) {
            int kt = (it + 1) * KT;
            #pragma unroll
            for (int r = 0; r < 2; r++) {
                int idx = tid + r * 256;
                int m = idx >> 2, k4 = (idx & 3) * 4;
                cp16(&A_s[s ^ 1][m][k4], A + (size_t)(tok0 + m) * MID_ + kt + k4);
            }
            {
                int n = tid >> 2, k4 = (tid & 3) * 4;
                cp16(&B_s[s ^ 1][n][k4], Bw + (size_t)(nblk + n) * MID_ + kt + k4);
            }
            CP_COMMIT();
            CP_WAIT1();
        } else {
            CP_WAIT0();
        }
        __syncthreads();

        #pragma unroll
        for (int ks = 0; ks < 2; ks++) {
            int k0 = ks * 8;
            uint32_t a[2][4];
            #pragma unroll
            for (int mi = 0; mi < 2; mi++) {
                int r0 = mb + mi * 16 + gr;
                a[mi][0] = __float_as_uint(to_tf32(A_s[s][r0    ][k0 + gc    ]));
                a[mi][1] = __float_as_uint(to_tf32(A_s[s][r0 + 8][k0 + gc    ]));
                a[mi][2] = __float_as_uint(to_tf32(A_s[s][r0    ][k0 + gc + 4]));
                a[mi][3] = __float_as_uint(to_tf32(A_s[s][r0 + 8][k0 + gc + 4]));
            }
            #pragma unroll
            for (int ni = 0; ni < 4; ni++) {
                int n0 = nb + ni * 8 + gr;
                uint32_t b0 = __float_as_uint(to_tf32(B_s[s][n0][k0 + gc    ]));
                uint32_t b1 = __float_as_uint(to_tf32(B_s[s][n0][k0 + gc + 4]));
                mma_tf32(acc[0][ni], a[0], b0, b1);
                mma_tf32(acc[1][ni], a[1], b0, b1);
            }
        }
        __syncthreads();
    }

    #pragma unroll
    for (int mi = 0; mi < 2; mi++) {
        int row = tok0 + mb + mi * 16 + gr;
        #pragma unroll
        for (int ni = 0; ni < 4; ni++) {
            int col = nblk + nb + ni * 8 + gc * 2;
            float bz0 = bias[col], bz1 = bias[col + 1];
            size_t i0 = (size_t)row * Ntot + col;
            size_t i1 = (size_t)(row + 8) * Ntot + col;
            float v00 = acc[mi][ni][0] + bz0, v01 = acc[mi][ni][1] + bz1;
            float v10 = acc[mi][ni][2] + bz0, v11 = acc[mi][ni][3] + bz1;
            if (resid) {
                v00 += resid[i0]; v01 += resid[i0 + 1];
                v10 += resid[i1]; v11 += resid[i1 + 1];
            }
            out[i0] = v00; out[i0 + 1] = v01;
            out[i1] = v10; out[i1 + 1] = v11;
        }
    }
}

// ===========================================================================
// Kernel 6: fused FiLM + 7x7 circular convolution, smem-tiled.
// ===========================================================================
__global__ __launch_bounds__(256) void film_circconv_kernel()
{
    const int TS = 16, HALO = 22, CPG = 16, PSTR = 20; // pixel stride (floats)
    __shared__ __align__(16) float halo_s[HALO * HALO * PSTR]; // 38720 B
    __shared__ __align__(16) float d_s[NTAP * CPG];            //  3136 B

    int tid = threadIdx.x;
    int tile = blockIdx.x;           // 0..15
    int cg   = blockIdx.y;           // 0..5
    int b    = blockIdx.z;           // 0..7
    int i0 = (tile >> 2) * TS, j0 = (tile & 3) * TS;
    int ch0 = cg * CPG;

    // ---- load dyn filter (transpose [c][tap] -> smem [tap][c]) ----
    const float* dynb = g_dyn + ((size_t)b * MID_ + ch0) * NTAP;
    for (int e = tid; e < CPG * NTAP; e += 256) {
        int c = e / NTAP, tap = e % NTAP;
        d_s[tap * CPG + c] = dynb[e];
    }

    // ---- load halo with FiLM applied: common = x*(1+gamma)+beta ----
    for (int e = tid; e < HALO * HALO * 4; e += 256) {
        int pix = e >> 2, c4 = e & 3;
        int li = pix / HALO, lj = pix % HALO;
        int ii = (i0 - 3 + li) & 63;
        int jj = (j0 - 3 + lj) & 63;
        size_t token = (size_t)((b << 12) | (ii << 6) | jj);
        int ch = ch0 + c4 * 4;
        float4 xv = *reinterpret_cast<const float4*>(g_x_emb + token * MID_ + ch);
        float4 gm = *reinterpret_cast<const float4*>(g_style + token * (2*MID_) + ch);
        float4 bt = *reinterpret_cast<const float4*>(g_style + token * (2*MID_) + MID_ + ch);
        float4 cv;
        cv.x = xv.x * (1.f + gm.x) + bt.x;
        cv.y = xv.y * (1.f + gm.y) + bt.y;
        cv.z = xv.z * (1.f + gm.z) + bt.z;
        cv.w = xv.w * (1.f + gm.w) + bt.w;
        *reinterpret_cast<float4*>(halo_s + pix * PSTR + c4 * 4) = cv;
    }
    __syncthreads();

    // ---- compute: thread = one output pixel ----
    int pi = tid >> 4, pj = tid & 15;
    size_t tok_out = (size_t)((b << 12) | ((i0 + pi) << 6) | (j0 + pj));
    float* outp = g_conv + tok_out * MID_ + ch0;

    #pragma unroll
    for (int c4 = 0; c4 < 4; c4++) {
        float4 acc = make_float4(0.f, 0.f, 0.f, 0.f);
        #pragma unroll
        for (int di = 0; di < 7; di++) {
            int hi = pi + 6 - di;
            #pragma unroll
            for (int dj = 0; dj < 7; dj++) {
                int hj = pj + 6 - dj;
                float4 v = *reinterpret_cast<const float4*>(
                    halo_s + (hi * HALO + hj) * PSTR + c4 * 4);
                float4 d = *reinterpret_cast<const float4*>(
                    d_s + (di * 7 + dj) * CPG + c4 * 4);
                acc.x += d.x * v.x; acc.y += d.y * v.y;
                acc.z += d.z * v.z; acc.w += d.w * v.w;
            }
        }
        *reinterpret_cast<float4*>(outp + c4 * 4) = acc;
    }
}

// ===========================================================================
extern "C" void kernel_launch(void* const* d_in, const int* in_sizes, int n_in,
                              void* d_out, int out_size)
{
    const float* x      = (const float*)d_in[0];
    const float* t      = (const float*)d_in[1];
    const float* ln_w   = (const float*)d_in[2];
    const float* ln_b   = (const float*)d_in[3];
    const float* down_w = (const float*)d_in[4];
    const float* down_b = (const float*)d_in[5];
    const float* ln1_w  = (const float*)d_in[6];
    const float* ln1_b  = (const float*)d_in[7];
    const float* down1_w= (const float*)d_in[8];
    const float* down1_b= (const float*)d_in[9];
    const float* dw_w   = (const float*)d_in[10];
    const float* dw_b   = (const float*)d_in[11];
    const float* pw_w   = (const float*)d_in[12];
    const float* pw_b   = (const float*)d_in[13];
    const float* m1w    = (const float*)d_in[14];
    const float* m1b    = (const float*)d_in[15];
    const float* m2w    = (const float*)d_in[16];
    const float* m2b    = (const float*)d_in[17];
    const float* basis  = (const float*)d_in[18];
    const float* up_w   = (const float*)d_in[19];
    const float* up_b   = (const float*)d_in[20];
    float* out = (float*)d_out;

    float *p_x_emb, *p_t_emb, *p_y, *p_style, *p_conv;
    cudaGetSymbolAddress((void**)&p_x_emb,  g_x_emb);
    cudaGetSymbolAddress((void**)&p_t_emb,  g_t_emb);
    cudaGetSymbolAddress((void**)&p_y,      g_y);
    cudaGetSymbolAddress((void**)&p_style,  g_style);
    cudaGetSymbolAddress((void**)&p_conv,   g_conv);

    // down / down1 (fused LN + GEMM, tf32 tensor cores, cp.async pipelined)
    ln_down_tc<<<TOK_/128, 256>>>(x, ln_w,  ln_b,  down_w,  down_b,  p_x_emb);
    ln_down_tc<<<TOK_/128, 256>>>(t, ln1_w, ln1_b, down1_w, down1_b, p_t_emb);

    // head path first (pw stays in the ncu -s5 slot)
    dw_silu_kernel<<<(TOK_*MID_)/256, 256>>>(dw_w, dw_b);
    gemm_k96_tc<<<dim3(TOK_/128, (2*MID_)/64), 256>>>(
        p_y, pw_w, pw_b, nullptr, p_style, 2*MID_);

    // FDS weights path (independent of head path)
    gsum_kernel<<<B_*32, 96>>>();
    mlp_dyn_kernel<<<B_, 256>>>(m1w, m1b, m2w, m2b, basis);

    // fused FiLM + 7x7 circular conv (smem-tiled)
    film_circconv_kernel<<<dim3(16, 6, 8), 256>>>();

    // up projection + residual
    gemm_k96_tc<<<dim3(TOK_/128, DIM_/64), 256>>>(
        p_conv, up_w, up_b, x, out, DIM_);
}

// round 17
// speedup vs baseline: 1.1280x; 1.0754x over previous
#include <cuda_runtime.h>
#include <cuda_fp16.h>
#include <stdint.h>
#include <math.h>

#define B_   8
#define H_   64
#define W_   64
#define DIM_ 768
#define MID_ 96
#define HW_  (H_*W_)            // 4096
#define TOK_ (B_*HW_)           // 32768
#define NTAP 49                 // 7x7

// ---------------- scratch (device globals: no allocation allowed) ----------
__device__ float  g_x_emb [TOK_*MID_];
__device__ float  g_t_emb [TOK_*MID_];
__device__ __half g_y_h   [TOK_*MID_];
__device__ float  g_style [TOK_*2*MID_];
__device__ __half g_conv_h[TOK_*MID_];
__device__ float  g_part  [B_*32*MID_];
__device__ float  g_dyn   [B_*MID_*NTAP]; // [b][c][tap]
__device__ __half g_pw_h  [2*MID_*MID_];  // fp16 pw weights
__device__ __half g_up_h  [DIM_*MID_];    // fp16 up weights

// ---------------- mma + cp.async helpers -----------------------------------
__device__ __forceinline__ float to_tf32(float x) {
    uint32_t u;
    asm("cvt.rna.tf32.f32 %0, %1;" : "=r"(u) : "f"(x));
    return __uint_as_float(u);
}

__device__ __forceinline__ void mma_tf32(float* c, const uint32_t* a,
                                         uint32_t b0, uint32_t b1) {
    asm volatile(
        "mma.sync.aligned.m16n8k8.row.col.f32.tf32.tf32.f32 "
        "{%0,%1,%2,%3}, {%4,%5,%6,%7}, {%8,%9}, {%0,%1,%2,%3};"
        : "+f"(c[0]), "+f"(c[1]), "+f"(c[2]), "+f"(c[3])
        : "r"(a[0]), "r"(a[1]), "r"(a[2]), "r"(a[3]), "r"(b0), "r"(b1));
}

__device__ __forceinline__ void mma_f16(float* c, const uint32_t* a,
                                        uint32_t b0, uint32_t b1) {
    asm volatile(
        "mma.sync.aligned.m16n8k16.row.col.f32.f16.f16.f32 "
        "{%0,%1,%2,%3}, {%4,%5,%6,%7}, {%8,%9}, {%0,%1,%2,%3};"
        : "+f"(c[0]), "+f"(c[1]), "+f"(c[2]), "+f"(c[3])
        : "r"(a[0]), "r"(a[1]), "r"(a[2]), "r"(a[3]), "r"(b0), "r"(b1));
}

__device__ __forceinline__ void cp16(void* dst_smem, const void* src) {
    uint32_t d = (uint32_t)__cvta_generic_to_shared(dst_smem);
    asm volatile("cp.async.cg.shared.global [%0], [%1], 16;" :: "r"(d), "l"(src));
}
#define CP_COMMIT() asm volatile("cp.async.commit_group;")
#define CP_WAIT1()  asm volatile("cp.async.wait_group 1;")
#define CP_WAIT0()  asm volatile("cp.async.wait_group 0;")

// ===========================================================================
// Kernel 1: fused LayerNorm(768) + Linear(768->96), tf32 TC (R10 config).
// ===========================================================================
__global__ __launch_bounds__(256) void ln_down_tc(
    const float* __restrict__ X, const float* __restrict__ lnw,
    const float* __restrict__ lnb, const float* __restrict__ Wd,
    const float* __restrict__ bd, float* __restrict__ out)
{
    const int TM = 128, KT = 16, LDS_ = KT + 4;
    const int NIT = DIM_ / KT;                    // 48
    __shared__ __align__(16) float A_s[2][TM][LDS_];
    __shared__ __align__(16) float B_s[2][MID_][LDS_];
    __shared__ float mean_s[TM], rstd_s[TM];
    __shared__ float lnw_s[DIM_], lnb_s[DIM_];

    int tid  = threadIdx.x;
    int tok0 = blockIdx.x * TM;

    {
        #pragma unroll
        for (int r = 0; r < 2; r++) {
            int idx = tid + r * 256;
            int m = idx >> 2, k4 = (idx & 3) * 4;
            cp16(&A_s[0][m][k4], X + (size_t)(tok0 + m) * DIM_ + k4);
        }
        for (int idx = tid; idx < 384; idx += 256) {
            int n = idx >> 2, k4 = (idx & 3) * 4;
            cp16(&B_s[0][n][k4], Wd + (size_t)n * DIM_ + k4);
        }
        CP_COMMIT();
    }

    for (int i = tid; i < DIM_; i += 256) { lnw_s[i] = lnw[i]; lnb_s[i] = lnb[i]; }

    int w = tid >> 5, lane = tid & 31;
    for (int m = w; m < TM; m += 8) {
        const float* row = X + (size_t)(tok0 + m) * DIM_;
        float s = 0.f, s2 = 0.f;
        #pragma unroll 4
        for (int k = lane; k < DIM_; k += 32) { float v = row[k]; s += v; s2 += v*v; }
        #pragma unroll
        for (int off = 16; off; off >>= 1) {
            s  += __shfl_down_sync(0xffffffffu, s,  off);
            s2 += __shfl_down_sync(0xffffffffu, s2, off);
        }
        if (lane == 0) {
            float mu  = s  * (1.f / DIM_);
            float var = s2 * (1.f / DIM_) - mu * mu;
            mean_s[m] = mu;
            rstd_s[m] = rsqrtf(var + 1e-6f);
        }
    }
    __syncthreads();

    int wm = w & 3, wn = w >> 2;
    int mb = wm * 32, nb = wn * 48;
    int gr = lane >> 2, gc = lane & 3;

    float acc[2][6][4];
    #pragma unroll
    for (int i = 0; i < 2; i++)
        #pragma unroll
        for (int j = 0; j < 6; j++)
            #pragma unroll
            for (int r = 0; r < 4; r++) acc[i][j][r] = 0.f;

    for (int it = 0; it < NIT; it++) {
        int s = it & 1;
        if (it + 1 < NIT) {
            int kt = (it + 1) * KT;
            #pragma unroll
            for (int r = 0; r < 2; r++) {
                int idx = tid + r * 256;
                int m = idx >> 2, k4 = (idx & 3) * 4;
                cp16(&A_s[s ^ 1][m][k4], X + (size_t)(tok0 + m) * DIM_ + kt + k4);
            }
            for (int idx = tid; idx < 384; idx += 256) {
                int n = idx >> 2, k4 = (idx & 3) * 4;
                cp16(&B_s[s ^ 1][n][k4], Wd + (size_t)n * DIM_ + kt + k4);
            }
            CP_COMMIT();
            CP_WAIT1();
        } else {
            CP_WAIT0();
        }
        __syncthreads();

        int kt = it * KT;
        #pragma unroll
        for (int ks = 0; ks < 2; ks++) {
            int k0 = ks * 8;
            float w0 = lnw_s[kt + k0 + gc],     bb0 = lnb_s[kt + k0 + gc];
            float w4 = lnw_s[kt + k0 + gc + 4], bb4 = lnb_s[kt + k0 + gc + 4];
            uint32_t a[2][4];
            #pragma unroll
            for (int mi = 0; mi < 2; mi++) {
                int r0 = mb + mi * 16 + gr;
                float mu0 = mean_s[r0],     rs0 = rstd_s[r0];
                float mu8 = mean_s[r0 + 8], rs8 = rstd_s[r0 + 8];
                a[mi][0] = __float_as_uint(to_tf32((A_s[s][r0    ][k0 + gc    ] - mu0) * rs0 * w0 + bb0));
                a[mi][1] = __float_as_uint(to_tf32((A_s[s][r0 + 8][k0 + gc    ] - mu8) * rs8 * w0 + bb0));
                a[mi][2] = __float_as_uint(to_tf32((A_s[s][r0    ][k0 + gc + 4] - mu0) * rs0 * w4 + bb4));
                a[mi][3] = __float_as_uint(to_tf32((A_s[s][r0 + 8][k0 + gc + 4] - mu8) * rs8 * w4 + bb4));
            }
            #pragma unroll
            for (int ni = 0; ni < 6; ni++) {
                int n0 = nb + ni * 8 + gr;
                uint32_t b0 = __float_as_uint(to_tf32(B_s[s][n0][k0 + gc    ]));
                uint32_t b1 = __float_as_uint(to_tf32(B_s[s][n0][k0 + gc + 4]));
                mma_tf32(acc[0][ni], a[0], b0, b1);
                mma_tf32(acc[1][ni], a[1], b0, b1);
            }
        }
        __syncthreads();
    }

    #pragma unroll
    for (int mi = 0; mi < 2; mi++) {
        int row = tok0 + mb + mi * 16 + gr;
        #pragma unroll
        for (int ni = 0; ni < 6; ni++) {
            int col = nb + ni * 8 + gc * 2;
            float bz0 = bd[col], bz1 = bd[col + 1];
            out[(size_t)row       * MID_ + col    ] = acc[mi][ni][0] + bz0;
            out[(size_t)row       * MID_ + col + 1] = acc[mi][ni][1] + bz1;
            out[(size_t)(row + 8) * MID_ + col    ] = acc[mi][ni][2] + bz0;
            out[(size_t)(row + 8) * MID_ + col + 1] = acc[mi][ni][3] + bz1;
        }
    }
}

// ===========================================================================
// Kernel 2: gvec partial sums (deterministic)
// ===========================================================================
__global__ void gsum_kernel()
{
    int b = blockIdx.x >> 5;
    int chunk = blockIdx.x & 31;
    int c = threadIdx.x;
    int tok0 = b * HW_ + chunk * 128;
    float s = 0.f;
    #pragma unroll 4
    for (int m = 0; m < 128; m++) s += g_x_emb[(size_t)(tok0 + m) * MID_ + c];
    g_part[(b * 32 + chunk) * MID_ + c] = s;
}

// ===========================================================================
// Kernel 3: per-batch MLP -> softmax -> dyn[b][c][tap]
// ===========================================================================
__global__ __launch_bounds__(256) void mlp_dyn_kernel(
    const float* __restrict__ m1w, const float* __restrict__ m1b,
    const float* __restrict__ m2w, const float* __restrict__ m2b,
    const float* __restrict__ basis)
{
    __shared__ float psum[2 * MID_];
    __shared__ float gvec[MID_];
    __shared__ float hid[24];
    __shared__ float wts[4];
    int b = blockIdx.x, tid = threadIdx.x;
    int w = tid >> 5, lane = tid & 31;

    if (tid < 2 * MID_) {
        int c = tid % MID_, half = tid / MID_;
        float s = 0.f;
        #pragma unroll
        for (int ch = 0; ch < 16; ch++)
            s += g_part[(b * 32 + half * 16 + ch) * MID_ + c];
        psum[tid] = s;
    }
    __syncthreads();
    if (tid < MID_) gvec[tid] = (psum[tid] + psum[MID_ + tid]) * (1.f / HW_);
    __syncthreads();

    #pragma unroll
    for (int sub = 0; sub < 3; sub++) {
        int h = w * 3 + sub;
        const float* wr = m1w + h * MID_;
        float s = gvec[lane] * wr[lane]
                + gvec[lane + 32] * wr[lane + 32]
                + gvec[lane + 64] * wr[lane + 64];
        #pragma unroll
        for (int off = 16; off; off >>= 1)
            s += __shfl_down_sync(0xffffffffu, s, off);
        if (lane == 0) hid[h] = fmaxf(s + m1b[h], 0.f);
    }
    __syncthreads();

    if (tid < 4) {
        float s = m2b[tid];
        #pragma unroll
        for (int h = 0; h < 24; h++) s += hid[h] * m2w[tid * 24 + h];
        wts[tid] = s;
    }
    __syncthreads();
    if (tid == 0) {
        float mx = fmaxf(fmaxf(wts[0], wts[1]), fmaxf(wts[2], wts[3]));
        float e0 = expf(wts[0]-mx), e1 = expf(wts[1]-mx);
        float e2 = expf(wts[2]-mx), e3 = expf(wts[3]-mx);
        float inv = 1.f / (e0 + e1 + e2 + e3);
        wts[0] = e0*inv; wts[1] = e1*inv; wts[2] = e2*inv; wts[3] = e3*inv;
    }
    __syncthreads();
    float w0 = wts[0], w1 = wts[1], w2 = wts[2], w3 = wts[3];
    for (int idx = tid; idx < MID_ * NTAP; idx += 256) {
        float s = w0 * basis[(size_t)(0 * MID_ * NTAP) + idx]
                + w1 * basis[(size_t)(1 * MID_ * NTAP) + idx]
                + w2 * basis[(size_t)(2 * MID_ * NTAP) + idx]
                + w3 * basis[(size_t)(3 * MID_ * NTAP) + idx];
        g_dyn[(size_t)b * MID_ * NTAP + idx] = s;
    }
}

// ===========================================================================
// Kernel 4: depthwise 3x3 conv + SiLU -> fp16; tail blocks convert weights.
// grid = 12288 dw blocks + 360 conversion blocks.
// ===========================================================================
#define DW_BLOCKS ((TOK_*MID_)/256)        // 12288
#define CVT_PW    (2*MID_*MID_)            // 18432
#define CVT_UP    (DIM_*MID_)              // 73728
#define CVT_BLOCKS (((CVT_PW + CVT_UP) + 255) / 256)   // 360

__global__ __launch_bounds__(256) void dw_silu_kernel(
    const float* __restrict__ dww, const float* __restrict__ dwb,
    const float* __restrict__ pww, const float* __restrict__ upw)
{
    int tid = threadIdx.x;

    if (blockIdx.x >= DW_BLOCKS) {       // weight conversion tail
        int i = (blockIdx.x - DW_BLOCKS) * 256 + tid;
        if (i < CVT_PW) g_pw_h[i] = __float2half(pww[i]);
        else { int j = i - CVT_PW; if (j < CVT_UP) g_up_h[j] = __float2half(upw[j]); }
        return;
    }

    __shared__ float w_s[MID_ * 9];
    __shared__ float b_s[MID_];
    for (int i = tid; i < MID_ * 9; i += 256) w_s[i] = dww[i];
    if (tid < MID_) b_s[tid] = dwb[tid];
    __syncthreads();

    int e = blockIdx.x * 256 + tid;
    int c = e % MID_;
    int token = e / MID_;
    int b = token >> 12, i = (token >> 6) & 63, j = token & 63;
    float acc = b_s[c];
    #pragma unroll
    for (int di = -1; di <= 1; di++) {
        int ii = i + di;
        if (ii < 0 || ii > 63) continue;
        #pragma unroll
        for (int dj = -1; dj <= 1; dj++) {
            int jj = j + dj;
            if (jj < 0 || jj > 63) continue;
            acc += g_t_emb[(size_t)((b << 12) | (ii << 6) | jj) * MID_ + c]
                 * w_s[c * 9 + (di + 1) * 3 + (dj + 1)];
        }
    }
    g_y_h[e] = __float2half(acc / (1.f + __expf(-acc)));
}

// ===========================================================================
// Kernel 5: K=96 GEMM, fp16 m16n8k16, SINGLE-STAGE (whole K in smem).
// Block 128x64, 8 warps (4M x 2N), warp 32x32.  Zero mainloop barriers.
// ===========================================================================
__global__ __launch_bounds__(256, 4) void gemm_k96_h(
    const __half* __restrict__ A, const __half* __restrict__ Bw,
    const float* __restrict__ bias, const float* __restrict__ resid,
    float* __restrict__ out, int Ntot)
{
    const int TM = 128, TN = 64, KP = 104;   // padded halves: conflict-free
    __shared__ __align__(16) __half A_s[TM][KP];  // 26624 B
    __shared__ __align__(16) __half B_s[TN][KP];  // 13312 B

    int tid  = threadIdx.x;
    int tok0 = blockIdx.x * TM;
    int nblk = blockIdx.y * TN;

    // ---- load entire K=96 (12 x 16B segs per row) ----
    #pragma unroll
    for (int r = 0; r < 6; r++) {            // A: 128*12 = 1536 segs
        int idx = tid + r * 256;
        int m = idx / 12, seg = idx % 12;
        cp16(&A_s[m][seg * 8], A + (size_t)(tok0 + m) * MID_ + seg * 8);
    }
    #pragma unroll
    for (int r = 0; r < 3; r++) {            // B: 64*12 = 768 segs
        int idx = tid + r * 256;
        int n = idx / 12, seg = idx % 12;
        cp16(&B_s[n][seg * 8], Bw + (size_t)(nblk + n) * MID_ + seg * 8);
    }
    CP_COMMIT();
    CP_WAIT0();
    __syncthreads();

    int w = tid >> 5, lane = tid & 31;
    int wm = w & 3, wn = w >> 2;
    int mb = wm * 32, nb = wn * 32;
    int gr = lane >> 2, gc = lane & 3;

    float acc[2][4][4];
    #pragma unroll
    for (int i = 0; i < 2; i++)
        #pragma unroll
        for (int j = 0; j < 4; j++)
            #pragma unroll
            for (int r = 0; r < 4; r++) acc[i][j][r] = 0.f;

    #pragma unroll
    for (int ks = 0; ks < 6; ks++) {         // K16 steps, no barriers
        int kk = ks * 16;
        uint32_t a[2][4];
        #pragma unroll
        for (int mi = 0; mi < 2; mi++) {
            int r0 = mb + mi * 16 + gr;
            a[mi][0] = *reinterpret_cast<const uint32_t*>(&A_s[r0    ][kk + 2*gc    ]);
            a[mi][1] = *reinterpret_cast<const uint32_t*>(&A_s[r0 + 8][kk + 2*gc    ]);
            a[mi][2] = *reinterpret_cast<const uint32_t*>(&A_s[r0    ][kk + 2*gc + 8]);
            a[mi][3] = *reinterpret_cast<const uint32_t*>(&A_s[r0 + 8][kk + 2*gc + 8]);
        }
        #pragma unroll
        for (int ni = 0; ni < 4; ni++) {
            int n0 = nb + ni * 8 + gr;
            uint32_t b0 = *reinterpret_cast<const uint32_t*>(&B_s[n0][kk + 2*gc    ]);
            uint32_t b1 = *reinterpret_cast<const uint32_t*>(&B_s[n0][kk + 2*gc + 8]);
            mma_f16(acc[0][ni], a[0], b0, b1);
            mma_f16(acc[1][ni], a[1], b0, b1);
        }
    }

    #pragma unroll
    for (int mi = 0; mi < 2; mi++) {
        int row = tok0 + mb + mi * 16 + gr;
        #pragma unroll
        for (int ni = 0; ni < 4; ni++) {
            int col = nblk + nb + ni * 8 + gc * 2;
            float bz0 = bias[col], bz1 = bias[col + 1];
            size_t i0 = (size_t)row * Ntot + col;
            size_t i1 = (size_t)(row + 8) * Ntot + col;
            float v00 = acc[mi][ni][0] + bz0, v01 = acc[mi][ni][1] + bz1;
            float v10 = acc[mi][ni][2] + bz0, v11 = acc[mi][ni][3] + bz1;
            if (resid) {
                v00 += resid[i0]; v01 += resid[i0 + 1];
                v10 += resid[i1]; v11 += resid[i1 + 1];
            }
            out[i0] = v00; out[i0 + 1] = v01;
            out[i1] = v10; out[i1 + 1] = v11;
        }
    }
}

// ===========================================================================
// Kernel 6: fused FiLM + 7x7 circular convolution -> fp16 output
// ===========================================================================
__global__ __launch_bounds__(256) void film_circconv_kernel()
{
    const int TS = 16, HALO = 22, CPG = 16, PSTR = 20;
    __shared__ __align__(16) float halo_s[HALO * HALO * PSTR];
    __shared__ __align__(16) float d_s[NTAP * CPG];

    int tid = threadIdx.x;
    int tile = blockIdx.x;
    int cg   = blockIdx.y;
    int b    = blockIdx.z;
    int i0 = (tile >> 2) * TS, j0 = (tile & 3) * TS;
    int ch0 = cg * CPG;

    const float* dynb = g_dyn + ((size_t)b * MID_ + ch0) * NTAP;
    for (int e = tid; e < CPG * NTAP; e += 256) {
        int c = e / NTAP, tap = e % NTAP;
        d_s[tap * CPG + c] = dynb[e];
    }

    for (int e = tid; e < HALO * HALO * 4; e += 256) {
        int pix = e >> 2, c4 = e & 3;
        int li = pix / HALO, lj = pix % HALO;
        int ii = (i0 - 3 + li) & 63;
        int jj = (j0 - 3 + lj) & 63;
        size_t token = (size_t)((b << 12) | (ii << 6) | jj);
        int ch = ch0 + c4 * 4;
        float4 xv = *reinterpret_cast<const float4*>(g_x_emb + token * MID_ + ch);
        float4 gm = *reinterpret_cast<const float4*>(g_style + token * (2*MID_) + ch);
        float4 bt = *reinterpret_cast<const float4*>(g_style + token * (2*MID_) + MID_ + ch);
        float4 cv;
        cv.x = xv.x * (1.f + gm.x) + bt.x;
        cv.y = xv.y * (1.f + gm.y) + bt.y;
        cv.z = xv.z * (1.f + gm.z) + bt.z;
        cv.w = xv.w * (1.f + gm.w) + bt.w;
        *reinterpret_cast<float4*>(halo_s + pix * PSTR + c4 * 4) = cv;
    }
    __syncthreads();

    int pi = tid >> 4, pj = tid & 15;
    size_t tok_out = (size_t)((b << 12) | ((i0 + pi) << 6) | (j0 + pj));
    __half* outp = g_conv_h + tok_out * MID_ + ch0;

    #pragma unroll
    for (int c4 = 0; c4 < 4; c4++) {
        float4 acc = make_float4(0.f, 0.f, 0.f, 0.f);
        #pragma unroll
        for (int di = 0; di < 7; di++) {
            int hi = pi + 6 - di;
            #pragma unroll
            for (int dj = 0; dj < 7; dj++) {
                int hj = pj + 6 - dj;
                float4 v = *reinterpret_cast<const float4*>(
                    halo_s + (hi * HALO + hj) * PSTR + c4 * 4);
                float4 d = *reinterpret_cast<const float4*>(
                    d_s + (di * 7 + dj) * CPG + c4 * 4);
                acc.x += d.x * v.x; acc.y += d.y * v.y;
                acc.z += d.z * v.z; acc.w += d.w * v.w;
            }
        }
        __half2* o2 = reinterpret_cast<__half2*>(outp + c4 * 4);
        o2[0] = __floats2half2_rn(acc.x, acc.y);
        o2[1] = __floats2half2_rn(acc.z, acc.w);
    }
}

// ===========================================================================
extern "C" void kernel_launch(void* const* d_in, const int* in_sizes, int n_in,
                              void* d_out, int out_size)
{
    const float* x      = (const float*)d_in[0];
    const float* t      = (const float*)d_in[1];
    const float* ln_w   = (const float*)d_in[2];
    const float* ln_b   = (const float*)d_in[3];
    const float* down_w = (const float*)d_in[4];
    const float* down_b = (const float*)d_in[5];
    const float* ln1_w  = (const float*)d_in[6];
    const float* ln1_b  = (const float*)d_in[7];
    const float* down1_w= (const float*)d_in[8];
    const float* down1_b= (const float*)d_in[9];
    const float* dw_w   = (const float*)d_in[10];
    const float* dw_b   = (const float*)d_in[11];
    const float* pw_w   = (const float*)d_in[12];
    const float* pw_b   = (const float*)d_in[13];
    const float* m1w    = (const float*)d_in[14];
    const float* m1b    = (const float*)d_in[15];
    const float* m2w    = (const float*)d_in[16];
    const float* m2b    = (const float*)d_in[17];
    const float* basis  = (const float*)d_in[18];
    const float* up_w   = (const float*)d_in[19];
    const float* up_b   = (const float*)d_in[20];
    float* out = (float*)d_out;

    float *p_x_emb, *p_t_emb, *p_style;
    __half *p_y_h, *p_conv_h, *p_pw_h, *p_up_h;
    cudaGetSymbolAddress((void**)&p_x_emb,  g_x_emb);
    cudaGetSymbolAddress((void**)&p_t_emb,  g_t_emb);
    cudaGetSymbolAddress((void**)&p_style,  g_style);
    cudaGetSymbolAddress((void**)&p_y_h,    g_y_h);
    cudaGetSymbolAddress((void**)&p_conv_h, g_conv_h);
    cudaGetSymbolAddress((void**)&p_pw_h,   g_pw_h);
    cudaGetSymbolAddress((void**)&p_up_h,   g_up_h);

    // down / down1 (fused LN + GEMM, tf32)
    ln_down_tc<<<TOK_/128, 256>>>(x, ln_w,  ln_b,  down_w,  down_b,  p_x_emb);
    ln_down_tc<<<TOK_/128, 256>>>(t, ln1_w, ln1_b, down1_w, down1_b, p_t_emb);

    // head path + fp16 weight conversion tail blocks
    dw_silu_kernel<<<DW_BLOCKS + CVT_BLOCKS, 256>>>(dw_w, dw_b, pw_w, up_w);
    gemm_k96_h<<<dim3(TOK_/128, (2*MID_)/64), 256>>>(
        p_y_h, p_pw_h, pw_b, nullptr, p_style, 2*MID_);

    // FDS weights path
    gsum_kernel<<<B_*32, 96>>>();
    mlp_dyn_kernel<<<B_, 256>>>(m1w, m1b, m2w, m2b, basis);

    // fused FiLM + 7x7 circular conv
    film_circconv_kernel<<<dim3(16, 6, 8), 256>>>();

    // up projection + residual (fp16 GEMM)
    gemm_k96_h<<<dim3(TOK_/128, DIM_/64), 256>>>(
        p_conv_h, p_up_h, up_b, x, out, DIM_);
}